// round 4
// baseline (speedup 1.0000x reference)
#include <cuda_runtime.h>

#define N_MAX 50000
#define E_MAX 800000
#define IN_FEATS 128
#define HF 64

typedef unsigned long long ull;

// Scratch (device globals; no allocation allowed)
__device__ int   g_cnt[N_MAX];
__device__ int   g_off[N_MAX + 1];
__device__ int   g_cur[N_MAX];
__device__ int   g_bsum[256];
__device__ int   g_esrc[E_MAX];
__device__ float g_dinv[N_MAX];
__device__ float g_x[N_MAX * HF];
__device__ float g_f1[N_MAX * HF];
__device__ float g_f2[N_MAX * HF];
__device__ float g_M[HF * 192];

// ---- packed f32x2 helpers ---------------------------------------------------
__device__ __forceinline__ ull pk2(float x, float y) {
    ull r; asm("mov.b64 %0, {%1,%2};" : "=l"(r) : "f"(x), "f"(y)); return r;
}
__device__ __forceinline__ ull fma2(ull a, ull b, ull c) {
    ull d; asm("fma.rn.f32x2 %0, %1, %2, %3;" : "=l"(d) : "l"(a), "l"(b), "l"(c));
    return d;
}
__device__ __forceinline__ void upk2(ull v, float& lo, float& hi) {
    asm("mov.b64 {%0,%1}, %2;" : "=f"(lo), "=f"(hi) : "l"(v));
}

// ---------------------------------------------------------------------------
__global__ void zero_cnt_kernel(int n) {
    int i = blockIdx.x * blockDim.x + threadIdx.x;
    if (i < n) g_cnt[i] = 0;
}

__global__ void count_kernel(const int* __restrict__ dst, int e) {
    int i = blockIdx.x * blockDim.x + threadIdx.x;
    if (i < e) atomicAdd(&g_cnt[dst[i]], 1);
}

// ---- prefix scan over g_cnt -> g_off (exclusive) ----------------------------
__global__ void scan1_kernel(int n) {
    __shared__ int sh[256];
    int t = threadIdx.x;
    int i = blockIdx.x * 256 + t;
    int v = (i < n) ? g_cnt[i] : 0;
    sh[t] = v;
    __syncthreads();
#pragma unroll
    for (int o = 1; o < 256; o <<= 1) {
        int add = (t >= o) ? sh[t - o] : 0;
        __syncthreads();
        sh[t] += add;
        __syncthreads();
    }
    if (i < n) g_off[i] = sh[t] - v;
    if (t == 255) g_bsum[blockIdx.x] = sh[255];
}

__global__ void scan2_kernel(int nb) {
    __shared__ int sh[256];
    int t = threadIdx.x;
    int v = (t < nb) ? g_bsum[t] : 0;
    sh[t] = v;
    __syncthreads();
#pragma unroll
    for (int o = 1; o < 256; o <<= 1) {
        int add = (t >= o) ? sh[t - o] : 0;
        __syncthreads();
        sh[t] += add;
        __syncthreads();
    }
    if (t < nb) g_bsum[t] = sh[t] - v;
}

// scan3 + dinv fused
__global__ void scan3_kernel(int n, int e) {
    int i = blockIdx.x * blockDim.x + threadIdx.x;
    if (i < n) {
        int o = g_off[i] + g_bsum[i >> 8];
        g_off[i] = o;
        g_cur[i] = o;
        g_dinv[i] = rsqrtf(fmaxf((float)g_cnt[i], 1.0f));
    }
    if (i == 0) g_off[n] = e;
}

__global__ void fill_kernel(const int* __restrict__ src,
                            const int* __restrict__ dst, int e) {
    int i = blockIdx.x * blockDim.x + threadIdx.x;
    if (i < e) {
        int d = dst[i];
        int pos = atomicAdd(&g_cur[d], 1);
        g_esrc[pos] = src[i];
    }
}

// ---------------------------------------------------------------------------
// Gather SpMM with 2-deep index prefetch + unroll-by-2.
// fout[d] = fin[d] - dinv[d] * sum_{s in N(d)} dinv[s]*fin[s]
// step 0: g_x -> g_f1;  step 1: g_f1 -> g_f2.
__global__ __launch_bounds__(256) void spmm_kernel(int n, int step) {
    const float* fin = (step == 0) ? g_x : g_f1;
    float* fout      = (step == 0) ? g_f1 : g_f2;
    int w = (blockIdx.x * blockDim.x + threadIdx.x) >> 5;
    int lane = threadIdx.x & 31;
    if (w >= n) return;
    int beg = g_off[w];
    int end = g_off[w + 1];
    const float2* F = reinterpret_cast<const float2*>(fin);
    float2 acc = make_float2(0.f, 0.f);

    int j = beg;
    int sA = 0, sB = 0;
    if (j < end)     sA = __ldg(&g_esrc[j]);
    if (j + 1 < end) sB = __ldg(&g_esrc[j + 1]);
    while (j + 2 <= end) {
        float wA = __ldg(&g_dinv[sA]);
        float2 vA = F[sA * 32 + lane];
        float wB = __ldg(&g_dinv[sB]);
        float2 vB = F[sB * 32 + lane];
        int jn = j + 2;
        if (jn < end)     sA = __ldg(&g_esrc[jn]);
        if (jn + 1 < end) sB = __ldg(&g_esrc[jn + 1]);
        acc.x = fmaf(wA, vA.x, acc.x);
        acc.y = fmaf(wA, vA.y, acc.y);
        acc.x = fmaf(wB, vB.x, acc.x);
        acc.y = fmaf(wB, vB.y, acc.y);
        j = jn;
    }
    if (j < end) {  // at most one tail edge; its index is in sA
        float wt = __ldg(&g_dinv[sA]);
        float2 v = F[sA * 32 + lane];
        acc.x = fmaf(wt, v.x, acc.x);
        acc.y = fmaf(wt, v.y, acc.y);
    }

    float wd = g_dinv[w];
    float2 xv = F[w * 32 + lane];
    float2 r = make_float2(xv.x - wd * acc.x, xv.y - wd * acc.y);
    reinterpret_cast<float2*>(fout)[w * 32 + lane] = r;
}

// ---------------------------------------------------------------------------
// GEMM1: g_x = relu(features[n,128] @ W1[64,128]^T + b1)
// 256 threads, M-tile 128, N=64. Each thread: 4 rows x 8 cols (4 f32x2 pairs).
// A-tile stored duplicated ((a,a) per 64-bit word) so the inner loop has zero
// pack instructions: 16 FFMA2 + 8 LDS.64 per k.
__global__ __launch_bounds__(256) void gemm1_kernel(
    const float* __restrict__ A, const float* __restrict__ W1,
    const float* __restrict__ b1, int n) {
    __shared__ ull   As2[32][132];
    __shared__ float Bs[32][68];
    int t = threadIdx.x;
    int m0 = blockIdx.x * 128;
    int tx = t & 7, ty = t >> 3;       // tx: 8 col-groups, ty: 32 row-groups
    int kv = t & 7, m4 = t >> 3;       // A-load mapping

    ull acc2[4][4];
#pragma unroll
    for (int i = 0; i < 4; i++)
#pragma unroll
        for (int j = 0; j < 4; j++) acc2[i][j] = 0ull;

    for (int k0 = 0; k0 < IN_FEATS; k0 += 32) {
#pragma unroll
        for (int i = 0; i < 4; i++) {
            int m = m4 * 4 + i;
            int gm = m0 + m;
            float4 v = make_float4(0.f, 0.f, 0.f, 0.f);
            if (gm < n)
                v = *reinterpret_cast<const float4*>(A + (size_t)gm * IN_FEATS + k0 + kv * 4);
            As2[kv * 4 + 0][m] = pk2(v.x, v.x);
            As2[kv * 4 + 1][m] = pk2(v.y, v.y);
            As2[kv * 4 + 2][m] = pk2(v.z, v.z);
            As2[kv * 4 + 3][m] = pk2(v.w, v.w);
        }
#pragma unroll
        for (int i = 0; i < 2; i++) {
            int fl = t * 2 + i;
            int nn = fl >> 3, kv2 = fl & 7;
            float4 v = *reinterpret_cast<const float4*>(W1 + (size_t)nn * IN_FEATS + k0 + kv2 * 4);
            Bs[kv2 * 4 + 0][nn] = v.x;
            Bs[kv2 * 4 + 1][nn] = v.y;
            Bs[kv2 * 4 + 2][nn] = v.z;
            Bs[kv2 * 4 + 3][nn] = v.w;
        }
        __syncthreads();
#pragma unroll
        for (int k = 0; k < 32; k++) {
            ull a0 = As2[k][ty * 4 + 0];
            ull a1 = As2[k][ty * 4 + 1];
            ull a2 = As2[k][ty * 4 + 2];
            ull a3 = As2[k][ty * 4 + 3];
            const ull* bp = reinterpret_cast<const ull*>(&Bs[k][tx * 8]);
            ull b0 = bp[0], b1v = bp[1], b2 = bp[2], b3 = bp[3];
            acc2[0][0] = fma2(a0, b0, acc2[0][0]);
            acc2[0][1] = fma2(a0, b1v, acc2[0][1]);
            acc2[0][2] = fma2(a0, b2, acc2[0][2]);
            acc2[0][3] = fma2(a0, b3, acc2[0][3]);
            acc2[1][0] = fma2(a1, b0, acc2[1][0]);
            acc2[1][1] = fma2(a1, b1v, acc2[1][1]);
            acc2[1][2] = fma2(a1, b2, acc2[1][2]);
            acc2[1][3] = fma2(a1, b3, acc2[1][3]);
            acc2[2][0] = fma2(a2, b0, acc2[2][0]);
            acc2[2][1] = fma2(a2, b1v, acc2[2][1]);
            acc2[2][2] = fma2(a2, b2, acc2[2][2]);
            acc2[2][3] = fma2(a2, b3, acc2[2][3]);
            acc2[3][0] = fma2(a3, b0, acc2[3][0]);
            acc2[3][1] = fma2(a3, b1v, acc2[3][1]);
            acc2[3][2] = fma2(a3, b2, acc2[3][2]);
            acc2[3][3] = fma2(a3, b3, acc2[3][3]);
        }
        __syncthreads();
    }
#pragma unroll
    for (int i = 0; i < 4; i++) {
        int gm = m0 + ty * 4 + i;
        if (gm < n) {
            float o[8];
#pragma unroll
            for (int j = 0; j < 4; j++) upk2(acc2[i][j], o[2 * j], o[2 * j + 1]);
#pragma unroll
            for (int j = 0; j < 8; j++) {
                float v = o[j] + b1[tx * 8 + j];
                o[j] = v > 0.f ? v : 0.f;
            }
            float4* dst = reinterpret_cast<float4*>(&g_x[(size_t)gm * HF + tx * 8]);
            dst[0] = make_float4(o[0], o[1], o[2], o[3]);
            dst[1] = make_float4(o[4], o[5], o[6], o[7]);
        }
    }
}

// ---------------------------------------------------------------------------
// Fold thetas into W2: M[r][p*64+c] = sum_j THETA[j][p] * W2[r][j*64+c]
__global__ void buildM_kernel(const float* __restrict__ W2) {
    int t = blockIdx.x * blockDim.x + threadIdx.x;
    if (t >= HF * 192) return;
    int r = t / 192, k = t % 192;
    int p = k >> 6, c = k & 63;
    const float cA[3] = {3.0f, -3.0f, 0.75f};
    const float cB[3] = {0.0f, 3.0f, -1.5f};
    const float cC[3] = {0.0f, 0.0f, 0.75f};
    g_M[t] = cA[p] * W2[r * 192 + c]
           + cB[p] * W2[r * 192 + 64 + c]
           + cC[p] * W2[r * 192 + 128 + c];
}

// GEMM2: out = [x | f1 | f2] @ M^T + b2   (K=192), same packed-f32x2 scheme
__global__ __launch_bounds__(256) void gemm2_kernel(
    const float* __restrict__ b2, float* __restrict__ out, int n) {
    __shared__ ull   As2[32][132];
    __shared__ float Bs[32][68];
    int t = threadIdx.x;
    int m0 = blockIdx.x * 128;
    int tx = t & 7, ty = t >> 3;
    int kv = t & 7, m4 = t >> 3;

    ull acc2[4][4];
#pragma unroll
    for (int i = 0; i < 4; i++)
#pragma unroll
        for (int j = 0; j < 4; j++) acc2[i][j] = 0ull;

#pragma unroll
    for (int cch = 0; cch < 6; cch++) {
        const float* S = (cch < 2) ? g_x : (cch < 4) ? g_f1 : g_f2;
        int koff = (cch & 1) * 32;
#pragma unroll
        for (int i = 0; i < 4; i++) {
            int m = m4 * 4 + i;
            int gm = m0 + m;
            float4 v = make_float4(0.f, 0.f, 0.f, 0.f);
            if (gm < n)
                v = *reinterpret_cast<const float4*>(S + (size_t)gm * HF + koff + kv * 4);
            As2[kv * 4 + 0][m] = pk2(v.x, v.x);
            As2[kv * 4 + 1][m] = pk2(v.y, v.y);
            As2[kv * 4 + 2][m] = pk2(v.z, v.z);
            As2[kv * 4 + 3][m] = pk2(v.w, v.w);
        }
#pragma unroll
        for (int i = 0; i < 2; i++) {
            int fl = t * 2 + i;
            int nn = fl >> 3, kv2 = fl & 7;
            float4 v = *reinterpret_cast<const float4*>(g_M + (size_t)nn * 192 + cch * 32 + kv2 * 4);
            Bs[kv2 * 4 + 0][nn] = v.x;
            Bs[kv2 * 4 + 1][nn] = v.y;
            Bs[kv2 * 4 + 2][nn] = v.z;
            Bs[kv2 * 4 + 3][nn] = v.w;
        }
        __syncthreads();
#pragma unroll
        for (int k = 0; k < 32; k++) {
            ull a0 = As2[k][ty * 4 + 0];
            ull a1 = As2[k][ty * 4 + 1];
            ull a2 = As2[k][ty * 4 + 2];
            ull a3 = As2[k][ty * 4 + 3];
            const ull* bp = reinterpret_cast<const ull*>(&Bs[k][tx * 8]);
            ull b0 = bp[0], b1v = bp[1], b2v = bp[2], b3 = bp[3];
            acc2[0][0] = fma2(a0, b0, acc2[0][0]);
            acc2[0][1] = fma2(a0, b1v, acc2[0][1]);
            acc2[0][2] = fma2(a0, b2v, acc2[0][2]);
            acc2[0][3] = fma2(a0, b3, acc2[0][3]);
            acc2[1][0] = fma2(a1, b0, acc2[1][0]);
            acc2[1][1] = fma2(a1, b1v, acc2[1][1]);
            acc2[1][2] = fma2(a1, b2v, acc2[1][2]);
            acc2[1][3] = fma2(a1, b3, acc2[1][3]);
            acc2[2][0] = fma2(a2, b0, acc2[2][0]);
            acc2[2][1] = fma2(a2, b1v, acc2[2][1]);
            acc2[2][2] = fma2(a2, b2v, acc2[2][2]);
            acc2[2][3] = fma2(a2, b3, acc2[2][3]);
            acc2[3][0] = fma2(a3, b0, acc2[3][0]);
            acc2[3][1] = fma2(a3, b1v, acc2[3][1]);
            acc2[3][2] = fma2(a3, b2v, acc2[3][2]);
            acc2[3][3] = fma2(a3, b3, acc2[3][3]);
        }
        __syncthreads();
    }
#pragma unroll
    for (int i = 0; i < 4; i++) {
        int gm = m0 + ty * 4 + i;
        if (gm < n) {
            float o[8];
#pragma unroll
            for (int j = 0; j < 4; j++) upk2(acc2[i][j], o[2 * j], o[2 * j + 1]);
#pragma unroll
            for (int j = 0; j < 8; j++) o[j] += b2[tx * 8 + j];
            float4* dst = reinterpret_cast<float4*>(&out[(size_t)gm * HF + tx * 8]);
            dst[0] = make_float4(o[0], o[1], o[2], o[3]);
            dst[1] = make_float4(o[4], o[5], o[6], o[7]);
        }
    }
}

// ---------------------------------------------------------------------------
extern "C" void kernel_launch(void* const* d_in, const int* in_sizes, int n_in,
                              void* d_out, int out_size) {
    const float* features = (const float*)d_in[0];
    const int*   src      = (const int*)d_in[1];
    const int*   dst      = (const int*)d_in[2];
    const float* W1       = (const float*)d_in[3];
    const float* b1       = (const float*)d_in[4];
    const float* W2       = (const float*)d_in[5];
    const float* b2       = (const float*)d_in[6];
    float* out = (float*)d_out;

    int n = in_sizes[0] / IN_FEATS;   // 50000
    int e = in_sizes[1];              // 800000
    int nb = (n + 255) / 256;         // 196

    zero_cnt_kernel<<<nb, 256>>>(n);
    count_kernel<<<(e + 255) / 256, 256>>>(dst, e);
    scan1_kernel<<<nb, 256>>>(n);
    scan2_kernel<<<1, 256>>>(nb);
    scan3_kernel<<<nb, 256>>>(n, e);
    fill_kernel<<<(e + 255) / 256, 256>>>(src, dst, e);

    gemm1_kernel<<<(n + 127) / 128, 256>>>(features, W1, b1, n);
    buildM_kernel<<<(HF * 192 + 255) / 256, 256>>>(W2);

    int spmm_blocks = (n + 7) / 8;    // 8 warps/block, warp per node
    spmm_kernel<<<spmm_blocks, 256>>>(n, 0);
    spmm_kernel<<<spmm_blocks, 256>>>(n, 1);

    gemm2_kernel<<<(n + 127) / 128, 256>>>(b2, out, n);
}